// round 15
// baseline (speedup 1.0000x reference)
#include <cuda_runtime.h>
#include <cuda_fp16.h>
#include <math.h>
#include <cstdint>

#define H_DIM 128
#define TEC 256        // edges per block (edge kernel)
#define PS1 68         // pair-row stride (uint32 units) for fp16x2 tiles

#define MAX_B 2
#define MAX_N 20000
#define MAX_BN (MAX_B * MAX_N)

// ---------------------------------------------------------------------------
// Scratch (allocation-free rule: __device__ globals)
// ---------------------------------------------------------------------------
__device__ __align__(128) uint32_t g_pre[4][(size_t)MAX_BN * 64]; // fp16x2 pairs
__device__ __align__(128) float g_hacc[2][(size_t)MAX_BN * H_DIM];
__device__ __align__(128) float g_einv[2][MAX_N];
__device__ __align__(128) float g_pos_upd[(size_t)MAX_BN * 3];
__device__ __align__(128) uint32_t g_CpFrag[2][8192];     // fp16 hi, paired-ntile uint4 layout
__device__ __align__(128) float g_bpc[2][H_DIM];
__device__ __align__(128) float g_bcu[2][H_DIM];
__device__ __align__(128) uint32_t g_preFrag[4][16384];   // fp16 hi/lo uint4 layout
__device__ __align__(128) uint32_t g_nodeFrag[4][16384];  // wu1top,Cu0,Cu1,wu2

// silu via single-MUFU tanh.approx: silu(x) = 0.5x + 0.5x*tanh(x/2)
__device__ __forceinline__ float silu_f(float v) {
    float t;
    asm("tanh.approx.f32 %0, %1;" : "=f"(t) : "f"(0.5f * v));
    float hv = 0.5f * v;
    return fmaf(hv, t, hv);
}
__device__ __forceinline__ float tanh_f(float v) {
    float t;
    asm("tanh.approx.f32 %0, %1;" : "=f"(t) : "f"(v));
    return t;
}

// ---- fp16 mma.sync helpers --------------------------------------------------
__device__ __forceinline__ void mma_f16(float c[4], const uint32_t a[4],
                                        uint32_t b0, uint32_t b1) {
    asm volatile(
        "mma.sync.aligned.m16n8k16.row.col.f32.f16.f16.f32 "
        "{%0,%1,%2,%3}, {%4,%5,%6,%7}, {%8,%9}, {%0,%1,%2,%3};"
        : "+f"(c[0]), "+f"(c[1]), "+f"(c[2]), "+f"(c[3])
        : "r"(a[0]), "r"(a[1]), "r"(a[2]), "r"(a[3]), "r"(b0), "r"(b1));
}
__device__ __forceinline__ uint32_t pack_hh(__half lo, __half hi) {
    __half2 h = __halves2half2(lo, hi);
    return *reinterpret_cast<uint32_t*>(&h);
}
__device__ __forceinline__ uint32_t pack_ff(float e, float o) {
    __half2 h = __floats2half2_rn(e, o);
    return *reinterpret_cast<uint32_t*>(&h);
}
__device__ __forceinline__ float2 up2(uint32_t v) {
    return __half22float2(*reinterpret_cast<__half2*>(&v));
}

// ---------------------------------------------------------------------------
// combine_kernel: grid (65, 4), 128 thr.
// ---------------------------------------------------------------------------
__global__ void combine_kernel(
    const float* __restrict__ w2u, const float* __restrict__ wp1u,
    const float* __restrict__ b2u, const float* __restrict__ bp1u,
    const float* __restrict__ w2d, const float* __restrict__ wp1d,
    const float* __restrict__ b2d, const float* __restrict__ bp1d,
    const float* __restrict__ wu1,
    uint32_t* __restrict__ CpFrag, uint32_t* __restrict__ nodeFrag,
    float* __restrict__ bpc, float* __restrict__ bcu)
{
    const float* wu1b = wu1 + 128 * H_DIM;
    const float* A; const float* Bm; const float* bvec; const float* badd;
    uint32_t* C; float* bout; bool split;
    switch (blockIdx.y) {
        case 0:  A = w2u; Bm = wp1u; bvec = b2u; badd = bp1u;
                 C = CpFrag;               bout = bpc;         split = false; break;
        case 1:  A = w2d; Bm = wp1d; bvec = b2d; badd = bp1d;
                 C = CpFrag + 8192;        bout = bpc + H_DIM; split = false; break;
        case 2:  A = w2u; Bm = wu1b; bvec = b2u; badd = 0;
                 C = nodeFrag + 1 * 16384; bout = bcu;         split = true;  break;
        default: A = w2d; Bm = wu1b; bvec = b2d; badd = 0;
                 C = nodeFrag + 2 * 16384; bout = bcu + H_DIM; split = true;  break;
    }
    int i2 = blockIdx.x;
    int j  = threadIdx.x;
    if (i2 == 64) {
        float s = 0.f;
        #pragma unroll 8
        for (int k = 0; k < H_DIM; ++k) s += bvec[k] * Bm[k * H_DIM + j];
        bout[j] = s + (badd ? badd[j] : 0.f);
        return;
    }
    float s0 = 0.f, s1 = 0.f;
    const float* a0r = A + (size_t)(2 * i2) * H_DIM;
    const float* a1r = a0r + H_DIM;
    #pragma unroll 8
    for (int k = 0; k < H_DIM; ++k) {
        float b = Bm[k * H_DIM + j];
        s0 += a0r[k] * b;
        s1 += a1r[k] * b;
    }
    int ks = i2 >> 3, m = i2 & 7;
    int lanep = m & 3, reg = m >> 2;
    int nn = j & 7;
    if (split) {
        __half h0 = __float2half_rn(s0), h1 = __float2half_rn(s1);
        __half l0 = __float2half_rn(s0 - __half2float(h0));
        __half l1 = __float2half_rn(s1 - __half2float(h1));
        int ntile = j >> 3;
        size_t base = ((size_t)(ntile * 8 + ks) * 32 + nn * 4 + lanep) * 4;
        C[base + reg]     = pack_hh(h0, h1);
        C[base + 2 + reg] = pack_hh(l0, l1);
    } else {
        int ntile = j >> 3, pass = ntile >> 3, ntl = ntile & 7;
        size_t idx = (size_t)pass * 4096
                   + ((size_t)(ks * 4 + (ntl >> 1)) * 32 + nn * 4 + lanep) * 4
                   + (ntl & 1) * 2 + reg;
        C[idx] = pack_ff(s0, s1);
    }
}

// ---------------------------------------------------------------------------
// fragw_kernel: grid (64, 6), 128 thr.
// ---------------------------------------------------------------------------
__global__ void fragw_kernel(const float* __restrict__ w1u,
                             const float* __restrict__ w1d,
                             const float* __restrict__ wu1,
                             const float* __restrict__ wu2,
                             uint32_t* __restrict__ preFrag,
                             uint32_t* __restrict__ nodeFrag)
{
    int y = blockIdx.y;
    const float* W; uint32_t* out;
    switch (y) {
        case 0: W = w1u;                out = preFrag;              break;
        case 1: W = w1u + 128 * H_DIM;  out = preFrag + 16384;      break;
        case 2: W = w1d;                out = preFrag + 2 * 16384;  break;
        case 3: W = w1d + 128 * H_DIM;  out = preFrag + 3 * 16384;  break;
        case 4: W = wu1;                out = nodeFrag;             break;
        default: W = wu2;               out = nodeFrag + 3 * 16384; break;
    }
    int i2 = blockIdx.x;
    int j  = threadIdx.x;
    float x0 = W[(size_t)(2 * i2) * H_DIM + j];
    float x1 = W[(size_t)(2 * i2 + 1) * H_DIM + j];
    __half h0 = __float2half_rn(x0), h1 = __float2half_rn(x1);
    __half l0 = __float2half_rn(x0 - __half2float(h0));
    __half l1 = __float2half_rn(x1 - __half2float(h1));
    int ks = i2 >> 3, m = i2 & 7;
    int lanep = m & 3, reg = m >> 2;
    int ntile = j >> 3, nn = j & 7;
    size_t base = ((size_t)(ntile * 8 + ks) * 32 + nn * 4 + lanep) * 4;
    out[base + reg]     = pack_hh(h0, h1);
    out[base + 2 + reg] = pack_hh(l0, l1);
}

// ---------------------------------------------------------------------------
// pre_mma_kernel: 128-row blocks; outputs fp16x2 (unchanged from R14)
// ---------------------------------------------------------------------------
__global__ void __launch_bounds__(256)
pre_mma_kernel(const float* __restrict__ feat, const uint32_t* __restrict__ frag,
               uint32_t* __restrict__ p0, uint32_t* __restrict__ p1,
               uint32_t* __restrict__ p2, uint32_t* __restrict__ p3, int nRows)
{
    extern __shared__ uint32_t smu[];
    uint32_t* sAhi = smu;                  // [128][68] pairs
    uint32_t* sAlo = sAhi + 128 * PS1;

    const int tid = threadIdx.x;
    const int wid = tid >> 5, lane = tid & 31;
    const int wg = wid >> 2;               // matrix half
    const int rw = wid & 3;                // 32-row group
    const int ar = rw * 32 + (lane >> 2);
    const int ak = lane & 3;
    const int g0 = blockIdx.x * 128;

    #pragma unroll
    for (int p = 0; p < 16; ++p) {
        int idx = p * 256 + tid;
        int r = idx >> 5, c4 = idx & 31;
        float4 v = make_float4(0.f, 0.f, 0.f, 0.f);
        if (g0 + r < nRows)
            v = __ldg((const float4*)feat + (size_t)(g0 + r) * 32 + c4);
        __half hx = __float2half_rn(v.x), hy = __float2half_rn(v.y);
        __half hz = __float2half_rn(v.z), hw = __float2half_rn(v.w);
        *(uint2*)(sAhi + r * PS1 + 2 * c4) =
            make_uint2(pack_hh(hx, hy), pack_hh(hz, hw));
        *(uint2*)(sAlo + r * PS1 + 2 * c4) = make_uint2(
            pack_ff(v.x - __half2float(hx), v.y - __half2float(hy)),
            pack_ff(v.z - __half2float(hz), v.w - __half2float(hw)));
    }
    __syncthreads();

    uint32_t* outs[4] = {p0, p1, p2, p3};

    #pragma unroll
    for (int m2 = 0; m2 < 2; ++m2) {
        int m = wg * 2 + m2;
        const uint4* Bm = (const uint4*)frag + (size_t)m * 4096;
        uint32_t* out = outs[m];
        #pragma unroll
        for (int pass = 0; pass < 2; ++pass) {
            float c[2][8][4];
            #pragma unroll
            for (int t = 0; t < 2; ++t)
                #pragma unroll
                for (int nt = 0; nt < 8; ++nt)
                    #pragma unroll
                    for (int q = 0; q < 4; ++q) c[t][nt][q] = 0.f;

            #pragma unroll 2
            for (int ks = 0; ks < 8; ++ks) {
                int kp = ks * 8 + ak;
                uint32_t ah0[4], al0[4], ah1[4], al1[4];
                ah0[0] = sAhi[ar * PS1 + kp];
                ah0[1] = sAhi[(ar + 8) * PS1 + kp];
                ah0[2] = sAhi[ar * PS1 + kp + 4];
                ah0[3] = sAhi[(ar + 8) * PS1 + kp + 4];
                al0[0] = sAlo[ar * PS1 + kp];
                al0[1] = sAlo[(ar + 8) * PS1 + kp];
                al0[2] = sAlo[ar * PS1 + kp + 4];
                al0[3] = sAlo[(ar + 8) * PS1 + kp + 4];
                ah1[0] = sAhi[(ar + 16) * PS1 + kp];
                ah1[1] = sAhi[(ar + 24) * PS1 + kp];
                ah1[2] = sAhi[(ar + 16) * PS1 + kp + 4];
                ah1[3] = sAhi[(ar + 24) * PS1 + kp + 4];
                al1[0] = sAlo[(ar + 16) * PS1 + kp];
                al1[1] = sAlo[(ar + 24) * PS1 + kp];
                al1[2] = sAlo[(ar + 16) * PS1 + kp + 4];
                al1[3] = sAlo[(ar + 24) * PS1 + kp + 4];
                #pragma unroll
                for (int nt = 0; nt < 8; ++nt) {
                    int ntile = pass * 8 + nt;
                    uint4 v = __ldg(Bm + (size_t)(ntile * 8 + ks) * 32 + lane);
                    mma_f16(c[0][nt], ah0, v.x, v.y);
                    mma_f16(c[0][nt], al0, v.x, v.y);
                    mma_f16(c[0][nt], ah0, v.z, v.w);
                    mma_f16(c[1][nt], ah1, v.x, v.y);
                    mma_f16(c[1][nt], al1, v.x, v.y);
                    mma_f16(c[1][nt], ah1, v.z, v.w);
                }
            }
            #pragma unroll
            for (int t = 0; t < 2; ++t) {
                int rowA = g0 + ar + t * 16, rowB = rowA + 8;
                #pragma unroll
                for (int nt = 0; nt < 8; ++nt) {
                    int cp = ((pass * 8 + nt) * 8 + 2 * ak) >> 1;  // uint32 index
                    if (rowA < nRows)
                        out[(size_t)rowA * 64 + cp] = pack_ff(c[t][nt][0], c[t][nt][1]);
                    if (rowB < nRows)
                        out[(size_t)rowB * 64 + cp] = pack_ff(c[t][nt][2], c[t][nt][3]);
                }
            }
        }
    }
}

// ---------------------------------------------------------------------------
// edge_mma_kernel: unchanged from R14 (256 edges/block, 2 CTAs/SM)
// ---------------------------------------------------------------------------
struct EdgeDir {
    const uint32_t* pre_a; const uint32_t* pre_b;   // fp16x2 rows (64 u32/row)
    const int* ei; const float* deg;
    const float* w1; const float* b1;
    const uint32_t* CpFrag; const float* bpc;
    const float* wp2; const float* bp2;
    float* hacc; float* einv;
};
struct EdgeParams { EdgeDir d[2]; };

__global__ void __launch_bounds__(256, 2)
edge_mma_kernel(EdgeParams P, const float* __restrict__ pos,
                float* __restrict__ pos_upd, int nE, int N)
{
    extern __shared__ uint32_t smu[];
    uint32_t* sHid = smu;                       // [256][68] fp16x2 pairs
    float* s_w1c = (float*)(smu + 256 * PS1);
    float* s_b1  = s_w1c + 128;
    float* s_bpc = s_b1 + 128;
    float* s_wp2 = s_bpc + 128;
    float* s_rel = s_wp2 + 128;                 // [256*3]
    float* s_dist= s_rel + 768;
    float* s_inv = s_dist + 256;
    float* s_p   = s_inv + 256;                 // [256]
    int*   s_src = (int*)(s_p + 256);
    int*   s_dst = s_src + 256;

    const EdgeDir& D = P.d[blockIdx.z];
    const int tid  = threadIdx.x;
    const int wid  = tid >> 5;
    const int lane = tid & 31;
    const int b    = blockIdx.y;
    const int e0   = blockIdx.x * TEC;
    const size_t bN = (size_t)b * N;

    {
        int e = e0 + tid;
        int s = 0, d = 0;
        float x0 = 0.f, x1 = 0.f, x2 = 0.f, dist = 0.f, inv = 0.f;
        if (e < nE) {
            s = D.ei[e];
            d = D.ei[nE + e];
            const float* ps = pos + (bN + s) * 3;
            const float* pd = pos + (bN + d) * 3;
            x0 = ps[0] - pd[0];
            x1 = ps[1] - pd[1];
            x2 = ps[2] - pd[2];
            dist = sqrtf(x0 * x0 + x1 * x1 + x2 * x2);
            inv  = 1.0f / fmaxf(D.deg[d], 1.0f);
        }
        s_src[tid] = s; s_dst[tid] = d;
        s_rel[tid * 3 + 0] = x0; s_rel[tid * 3 + 1] = x1; s_rel[tid * 3 + 2] = x2;
        s_dist[tid] = dist; s_inv[tid] = inv;
        if (tid < 128) {
            s_w1c[tid] = D.w1[256 * H_DIM + tid];
            s_b1[tid]  = D.b1[tid];
            s_bpc[tid] = D.bpc[tid];
            s_wp2[tid] = D.wp2[tid];
        }
    }
    __syncthreads();

    #pragma unroll
    for (int p = 0; p < 32; p += 4) {
        uint2 va[4], vb[4];
        #pragma unroll
        for (int q = 0; q < 4; ++q) {
            int r = (p + q) * 8 + wid;
            va[q] = __ldg((const uint2*)D.pre_a + (size_t)(bN + s_src[r]) * 32 + lane);
            vb[q] = __ldg((const uint2*)D.pre_b + (size_t)(bN + s_dst[r]) * 32 + lane);
        }
        #pragma unroll
        for (int q = 0; q < 4; ++q) {
            int r = (p + q) * 8 + wid;
            float dd = s_dist[r], inv = s_inv[r];
            float4 wc = *(const float4*)(s_w1c + lane * 4);
            float4 bb = *(const float4*)(s_b1 + lane * 4);
            float2 a01 = up2(va[q].x), a23 = up2(va[q].y);
            float2 b01 = up2(vb[q].x), b23 = up2(vb[q].y);
            float h0 = silu_f(a01.x + b01.x + dd * wc.x + bb.x);
            float h1 = silu_f(a01.y + b01.y + dd * wc.y + bb.y);
            float h2 = silu_f(a23.x + b23.x + dd * wc.z + bb.z);
            float h3 = silu_f(a23.y + b23.y + dd * wc.w + bb.w);
            *(uint2*)(sHid + r * PS1 + 2 * lane) =
                make_uint2(pack_ff(h0, h1), pack_ff(h2, h3));
            float* gp = D.hacc + (bN + s_dst[r]) * H_DIM + lane * 4;
            asm volatile("red.global.add.v4.f32 [%0], {%1, %2, %3, %4};"
                         :: "l"(gp), "f"(h0 * inv), "f"(h1 * inv),
                            "f"(h2 * inv), "f"(h3 * inv) : "memory");
        }
    }
    if (b == 0 && (e0 + tid) < nE)
        atomicAdd(&D.einv[s_dst[tid]], s_inv[tid]);
    __syncthreads();

    const int arb = wid * 32 + (lane >> 2);
    const int ak  = lane & 3;
    float sum[4] = {0.f, 0.f, 0.f, 0.f};
    const uint4* Cp4 = (const uint4*)D.CpFrag;

    #pragma unroll
    for (int pass = 0; pass < 2; ++pass) {
        float c[2][8][4];
        #pragma unroll
        for (int t = 0; t < 2; ++t)
            #pragma unroll
            for (int nt = 0; nt < 8; ++nt)
                #pragma unroll
                for (int q = 0; q < 4; ++q) c[t][nt][q] = 0.f;

        #pragma unroll 2
        for (int ks = 0; ks < 8; ++ks) {
            int kp = ks * 8 + ak;
            uint4 bv[4];
            #pragma unroll
            for (int ntp = 0; ntp < 4; ++ntp)
                bv[ntp] = __ldg(Cp4 + (size_t)pass * 1024
                                + (size_t)(ks * 4 + ntp) * 32 + lane);
            #pragma unroll
            for (int t = 0; t < 2; ++t) {
                int ar = arb + t * 16;
                uint32_t a[4];
                a[0] = sHid[ar * PS1 + kp];
                a[1] = sHid[(ar + 8) * PS1 + kp];
                a[2] = sHid[ar * PS1 + kp + 4];
                a[3] = sHid[(ar + 8) * PS1 + kp + 4];
                #pragma unroll
                for (int ntp = 0; ntp < 4; ++ntp) {
                    mma_f16(c[t][2 * ntp],     a, bv[ntp].x, bv[ntp].y);
                    mma_f16(c[t][2 * ntp + 1], a, bv[ntp].z, bv[ntp].w);
                }
            }
        }
        #pragma unroll
        for (int t = 0; t < 2; ++t) {
            #pragma unroll
            for (int nt = 0; nt < 8; ++nt) {
                int cb = pass * 64 + nt * 8 + 2 * ak;
                float w0 = s_wp2[cb], w1v = s_wp2[cb + 1];
                float q0 = s_bpc[cb], q1 = s_bpc[cb + 1];
                sum[2 * t]     += silu_f(c[t][nt][0] + q0) * w0
                                + silu_f(c[t][nt][1] + q1) * w1v;
                sum[2 * t + 1] += silu_f(c[t][nt][2] + q0) * w0
                                + silu_f(c[t][nt][3] + q1) * w1v;
            }
        }
    }

    #pragma unroll
    for (int i = 0; i < 4; ++i) {
        sum[i] += __shfl_xor_sync(0xFFFFFFFFu, sum[i], 1);
        sum[i] += __shfl_xor_sync(0xFFFFFFFFu, sum[i], 2);
    }
    if (ak == 0) {
        s_p[arb]      = sum[0];
        s_p[arb + 8]  = sum[1];
        s_p[arb + 16] = sum[2];
        s_p[arb + 24] = sum[3];
    }
    __syncthreads();

    if ((e0 + tid) < nE) {
        float w = tanh_f(s_p[tid] + D.bp2[0]);
        int d = s_dst[tid];
        float* pp = pos_upd + (bN + d) * 3;
        atomicAdd(&pp[0], w * s_rel[tid * 3 + 0]);
        atomicAdd(&pp[1], w * s_rel[tid * 3 + 1]);
        atomicAdd(&pp[2], w * s_rel[tid * 3 + 2]);
    }
}

// ---------------------------------------------------------------------------
// node2_mma_kernel v2: 128-row blocks; warp = (rw row-group of 32, cg ntile
// half of 8). Each B fragment load serves 32 rows (2x less redundancy).
// ---------------------------------------------------------------------------
__global__ void __launch_bounds__(256)
node2_mma_kernel(const float* __restrict__ feat,
                 const float* __restrict__ hacc0, const float* __restrict__ hacc1,
                 const uint32_t* __restrict__ nodeFrag,
                 const float* __restrict__ einv0, const float* __restrict__ einv1,
                 const float* __restrict__ bcu0, const float* __restrict__ bcu1,
                 const float* __restrict__ bu1,  const float* __restrict__ bu2,
                 float* __restrict__ outf, int N, int nRows)
{
    extern __shared__ uint32_t smu[];
    uint32_t* sAhi = smu;                   // [128][68]
    uint32_t* sAlo = sAhi + 128 * PS1;
    float* s_eU   = (float*)(smu + 2 * 128 * PS1);  // [128]
    float* s_eD   = s_eU + 128;
    float* s_bias = s_eD + 128;             // 4*128

    const int tid = threadIdx.x;
    const int wid = tid >> 5, lane = tid & 31;
    const int rw = wid & 3, cg = wid >> 2;
    const int arb = rw * 32 + (lane >> 2);
    const int ak = lane & 3;
    const int g0 = blockIdx.x * 128;

    if (tid < 128) {
        int g = g0 + tid;
        float eu = 0.f, ed = 0.f;
        if (g < nRows) {
            int node = g % N;
            eu = einv0[node];
            ed = einv1[node];
        }
        s_eU[tid] = eu; s_eD[tid] = ed;
        s_bias[tid]       = bu1[tid];
        s_bias[128 + tid] = bcu0[tid];
        s_bias[256 + tid] = bcu1[tid];
        s_bias[384 + tid] = bu2[tid];
    }

    // ---- layer 1: accumulate over 3 input matrices ----
    float c[2][8][4];
    #pragma unroll
    for (int t = 0; t < 2; ++t)
        #pragma unroll
        for (int nt = 0; nt < 8; ++nt)
            #pragma unroll
            for (int q = 0; q < 4; ++q) c[t][nt][q] = 0.f;

    for (int m = 0; m < 3; ++m) {
        const float* src = (m == 0) ? feat : (m == 1) ? hacc0 : hacc1;
        __syncthreads();
        #pragma unroll
        for (int p = 0; p < 16; ++p) {
            int idx = p * 256 + tid;
            int r = idx >> 5, c4 = idx & 31;
            float4 v = make_float4(0.f, 0.f, 0.f, 0.f);
            if (g0 + r < nRows)
                v = __ldg((const float4*)src + (size_t)(g0 + r) * 32 + c4);
            __half hx = __float2half_rn(v.x), hy = __float2half_rn(v.y);
            __half hz = __float2half_rn(v.z), hw = __float2half_rn(v.w);
            *(uint2*)(sAhi + r * PS1 + 2 * c4) =
                make_uint2(pack_hh(hx, hy), pack_hh(hz, hw));
            *(uint2*)(sAlo + r * PS1 + 2 * c4) = make_uint2(
                pack_ff(v.x - __half2float(hx), v.y - __half2float(hy)),
                pack_ff(v.z - __half2float(hz), v.w - __half2float(hw)));
        }
        __syncthreads();

        const uint4* Bm = (const uint4*)(nodeFrag + (size_t)m * 16384);
        #pragma unroll 2
        for (int ks = 0; ks < 8; ++ks) {
            int kp = ks * 8 + ak;
            uint32_t ah0[4], al0[4], ah1[4], al1[4];
            ah0[0] = sAhi[arb * PS1 + kp];
            ah0[1] = sAhi[(arb + 8) * PS1 + kp];
            ah0[2] = sAhi[arb * PS1 + kp + 4];
            ah0[3] = sAhi[(arb + 8) * PS1 + kp + 4];
            al0[0] = sAlo[arb * PS1 + kp];
            al0[1] = sAlo[(arb + 8) * PS1 + kp];
            al0[2] = sAlo[arb * PS1 + kp + 4];
            al0[3] = sAlo[(arb + 8) * PS1 + kp + 4];
            ah1[0] = sAhi[(arb + 16) * PS1 + kp];
            ah1[1] = sAhi[(arb + 24) * PS1 + kp];
            ah1[2] = sAhi[(arb + 16) * PS1 + kp + 4];
            ah1[3] = sAhi[(arb + 24) * PS1 + kp + 4];
            al1[0] = sAlo[(arb + 16) * PS1 + kp];
            al1[1] = sAlo[(arb + 24) * PS1 + kp];
            al1[2] = sAlo[(arb + 16) * PS1 + kp + 4];
            al1[3] = sAlo[(arb + 24) * PS1 + kp + 4];
            #pragma unroll
            for (int nt = 0; nt < 8; ++nt) {
                int ntile = cg * 8 + nt;
                uint4 v = __ldg(Bm + (size_t)(ntile * 8 + ks) * 32 + lane);
                mma_f16(c[0][nt], ah0, v.x, v.y);
                mma_f16(c[0][nt], al0, v.x, v.y);
                mma_f16(c[0][nt], ah0, v.z, v.w);
                mma_f16(c[1][nt], ah1, v.x, v.y);
                mma_f16(c[1][nt], al1, v.x, v.y);
                mma_f16(c[1][nt], ah1, v.z, v.w);
            }
        }
    }
    __syncthreads();
    // bias + silu -> hi/lo of h1 back into sAhi/sAlo
    {
        #pragma unroll
        for (int t = 0; t < 2; ++t) {
            int r0 = arb + t * 16, r1 = r0 + 8;
            float eu0 = s_eU[r0], ed0 = s_eD[r0];
            float eu1 = s_eU[r1], ed1 = s_eD[r1];
            #pragma unroll
            for (int nt = 0; nt < 8; ++nt) {
                int col = (cg * 8 + nt) * 8 + 2 * ak;
                int kp  = col >> 1;
                float bA = s_bias[col],        bB = s_bias[col + 1];
                float cA0 = s_bias[128 + col], cA1 = s_bias[128 + col + 1];
                float cB0 = s_bias[256 + col], cB1 = s_bias[256 + col + 1];
                float v00 = silu_f(c[t][nt][0] + bA + eu0 * cA0 + ed0 * cB0);
                float v01 = silu_f(c[t][nt][1] + bB + eu0 * cA1 + ed0 * cB1);
                float v10 = silu_f(c[t][nt][2] + bA + eu1 * cA0 + ed1 * cB0);
                float v11 = silu_f(c[t][nt][3] + bB + eu1 * cA1 + ed1 * cB1);
                __half h00 = __float2half_rn(v00), h01 = __float2half_rn(v01);
                __half h10 = __float2half_rn(v10), h11 = __float2half_rn(v11);
                sAhi[r0 * PS1 + kp] = pack_hh(h00, h01);
                sAhi[r1 * PS1 + kp] = pack_hh(h10, h11);
                sAlo[r0 * PS1 + kp] = pack_ff(
                    v00 - __half2float(h00), v01 - __half2float(h01));
                sAlo[r1 * PS1 + kp] = pack_ff(
                    v10 - __half2float(h10), v11 - __half2float(h11));
            }
        }
    }
    __syncthreads();

    // ---- layer 2 ----
    #pragma unroll
    for (int t = 0; t < 2; ++t)
        #pragma unroll
        for (int nt = 0; nt < 8; ++nt)
            #pragma unroll
            for (int q = 0; q < 4; ++q) c[t][nt][q] = 0.f;

    {
        const uint4* Bm = (const uint4*)(nodeFrag + (size_t)3 * 16384);
        #pragma unroll 2
        for (int ks = 0; ks < 8; ++ks) {
            int kp = ks * 8 + ak;
            uint32_t ah0[4], al0[4], ah1[4], al1[4];
            ah0[0] = sAhi[arb * PS1 + kp];
            ah0[1] = sAhi[(arb + 8) * PS1 + kp];
            ah0[2] = sAhi[arb * PS1 + kp + 4];
            ah0[3] = sAhi[(arb + 8) * PS1 + kp + 4];
            al0[0] = sAlo[arb * PS1 + kp];
            al0[1] = sAlo[(arb + 8) * PS1 + kp];
            al0[2] = sAlo[arb * PS1 + kp + 4];
            al0[3] = sAlo[(arb + 8) * PS1 + kp + 4];
            ah1[0] = sAhi[(arb + 16) * PS1 + kp];
            ah1[1] = sAhi[(arb + 24) * PS1 + kp];
            ah1[2] = sAhi[(arb + 16) * PS1 + kp + 4];
            ah1[3] = sAhi[(arb + 24) * PS1 + kp + 4];
            al1[0] = sAlo[(arb + 16) * PS1 + kp];
            al1[1] = sAlo[(arb + 24) * PS1 + kp];
            al1[2] = sAlo[(arb + 16) * PS1 + kp + 4];
            al1[3] = sAlo[(arb + 24) * PS1 + kp + 4];
            #pragma unroll
            for (int nt = 0; nt < 8; ++nt) {
                int ntile = cg * 8 + nt;
                uint4 v = __ldg(Bm + (size_t)(ntile * 8 + ks) * 32 + lane);
                mma_f16(c[0][nt], ah0, v.x, v.y);
                mma_f16(c[0][nt], al0, v.x, v.y);
                mma_f16(c[0][nt], ah0, v.z, v.w);
                mma_f16(c[1][nt], ah1, v.x, v.y);
                mma_f16(c[1][nt], al1, v.x, v.y);
                mma_f16(c[1][nt], ah1, v.z, v.w);
            }
        }
    }
    {
        #pragma unroll
        for (int t = 0; t < 2; ++t) {
            int gA = g0 + arb + t * 16, gB = gA + 8;
            #pragma unroll
            for (int nt = 0; nt < 8; ++nt) {
                int col = (cg * 8 + nt) * 8 + 2 * ak;
                float bA = s_bias[384 + col], bB = s_bias[384 + col + 1];
                if (gA < nRows) {
                    size_t o = (size_t)gA * H_DIM + col;
                    float2 f = *(const float2*)&feat[o];
                    *(float2*)&outf[o] = make_float2(
                        f.x + c[t][nt][0] + bA, f.y + c[t][nt][1] + bB);
                }
                if (gB < nRows) {
                    size_t o = (size_t)gB * H_DIM + col;
                    float2 f = *(const float2*)&feat[o];
                    *(float2*)&outf[o] = make_float2(
                        f.x + c[t][nt][2] + bA, f.y + c[t][nt][3] + bB);
                }
            }
        }
    }
}

__global__ void pos_kernel(const float* __restrict__ pos,
                           const float* __restrict__ pos_upd,
                           float* __restrict__ out, int n)
{
    int i = blockIdx.x * blockDim.x + threadIdx.x;
    if (i < n) out[i] = pos[i] + 0.5f * pos_upd[i];
}

extern "C" void kernel_launch(void* const* d_in, const int* in_sizes, int n_in,
                              void* d_out, int out_size)
{
    const float* feat   = (const float*)d_in[0];
    const float* pos    = (const float*)d_in[1];
    const int*   ei_up  = (const int*)d_in[2];
    const int*   ei_dn  = (const int*)d_in[3];
    const float* deg_up = (const float*)d_in[4];
    const float* deg_dn = (const float*)d_in[5];

    const float* w1u  = (const float*)d_in[6];
    const float* b1u  = (const float*)d_in[7];
    const float* w2u  = (const float*)d_in[8];
    const float* b2u  = (const float*)d_in[9];
    const float* wp1u = (const float*)d_in[10];
    const float* bp1u = (const float*)d_in[11];
    const float* wp2u = (const float*)d_in[12];
    const float* bp2u = (const float*)d_in[13];

    const float* w1d  = (const float*)d_in[14];
    const float* b1d  = (const float*)d_in[15];
    const float* w2d  = (const float*)d_in[16];
    const float* b2d  = (const float*)d_in[17];
    const float* wp1d = (const float*)d_in[18];
    const float* bp1d = (const float*)d_in[19];
    const float* wp2d = (const float*)d_in[20];
    const float* bp2d = (const float*)d_in[21];

    const float* wu1 = (const float*)d_in[22];
    const float* bu1 = (const float*)d_in[23];
    const float* wu2 = (const float*)d_in[24];
    const float* bu2 = (const float*)d_in[25];

    int E = in_sizes[2] / 2;
    int N = in_sizes[4];
    int B = in_sizes[0] / (N * H_DIM);
    int nRows = B * N;

    float *hacc, *einv, *pos_upd, *bpc, *bcu;
    uint32_t *pre, *CpFrag, *preFrag, *nodeFrag;
    cudaGetSymbolAddress((void**)&pre,      g_pre);
    cudaGetSymbolAddress((void**)&hacc,     g_hacc);
    cudaGetSymbolAddress((void**)&einv,     g_einv);
    cudaGetSymbolAddress((void**)&pos_upd,  g_pos_upd);
    cudaGetSymbolAddress((void**)&CpFrag,   g_CpFrag);
    cudaGetSymbolAddress((void**)&bpc,      g_bpc);
    cudaGetSymbolAddress((void**)&bcu,      g_bcu);
    cudaGetSymbolAddress((void**)&preFrag,  g_preFrag);
    cudaGetSymbolAddress((void**)&nodeFrag, g_nodeFrag);

    const size_t PS = (size_t)MAX_BN * 64;
    uint32_t* pre_au = pre;
    uint32_t* pre_bu = pre + PS;
    uint32_t* pre_ad = pre + 2 * PS;
    uint32_t* pre_bd = pre + 3 * PS;
    const size_t HPS = (size_t)MAX_BN * H_DIM;
    float* hacc_u = hacc;
    float* hacc_d = hacc + HPS;
    float* einv_u = einv;
    float* einv_d = einv + MAX_N;

    cudaMemsetAsync(hacc, 0, 2 * HPS * sizeof(float));
    cudaMemsetAsync(einv, 0, 2 * MAX_N * sizeof(float));
    cudaMemsetAsync(pos_upd, 0, (size_t)nRows * 3 * sizeof(float));

    int smemPre  = 2 * 128 * PS1 * 4;                           // 69632 B
    int smemEdge = 256 * PS1 * 4
                 + (512 + 768 + 256 + 256 + 256) * 4 + 512 * 4; // 79872 B
    int smemNode = (2 * 128 * PS1 + 256 + 512) * 4;             // 72704 B
    cudaFuncSetAttribute(pre_mma_kernel,
                         cudaFuncAttributeMaxDynamicSharedMemorySize, smemPre);
    cudaFuncSetAttribute(edge_mma_kernel,
                         cudaFuncAttributeMaxDynamicSharedMemorySize, smemEdge);
    cudaFuncSetAttribute(node2_mma_kernel,
                         cudaFuncAttributeMaxDynamicSharedMemorySize, smemNode);

    combine_kernel<<<dim3(65, 4), H_DIM>>>(
        w2u, wp1u, b2u, bp1u, w2d, wp1d, b2d, bp1d, wu1,
        CpFrag, nodeFrag, bpc, bcu);

    fragw_kernel<<<dim3(64, 6), H_DIM>>>(w1u, w1d, wu1, wu2,
                                         preFrag, nodeFrag);

    pre_mma_kernel<<<(nRows + 127) / 128, 256, smemPre>>>(
        feat, preFrag, pre_au, pre_bu, pre_ad, pre_bd, nRows);

    EdgeParams EP;
    EP.d[0] = { pre_au, pre_bu, ei_up, deg_up, w1u, b1u,
                CpFrag,        bpc,         wp2u, bp2u, hacc_u, einv_u };
    EP.d[1] = { pre_ad, pre_bd, ei_dn, deg_dn, w1d, b1d,
                CpFrag + 8192, bpc + H_DIM, wp2d, bp2d, hacc_d, einv_d };

    dim3 egrid((E + TEC - 1) / TEC, B, 2);
    edge_mma_kernel<<<egrid, 256, smemEdge>>>(EP, pos, pos_upd, E, N);

    node2_mma_kernel<<<(nRows + 127) / 128, 256, smemNode>>>(
        feat, hacc_u, hacc_d, nodeFrag, einv_u, einv_d,
        bcu, bcu + H_DIM, bu1, bu2, (float*)d_out, N, nRows);

    size_t featN = (size_t)nRows * H_DIM;
    int pn = nRows * 3;
    pos_kernel<<<(pn + 255) / 256, 256>>>(
        pos, pos_upd, (float*)d_out + featN, pn);
}

// round 16
// speedup vs baseline: 1.1081x; 1.1081x over previous
#include <cuda_runtime.h>
#include <cuda_fp16.h>
#include <math.h>
#include <cstdint>

#define H_DIM 128
#define TEC 256        // edges per block (edge kernel)
#define PS1 68         // pair-row stride (uint32 units) for fp16x2 tiles

#define MAX_B 2
#define MAX_N 20000
#define MAX_BN (MAX_B * MAX_N)

// ---------------------------------------------------------------------------
// Scratch (allocation-free rule: __device__ globals)
// ---------------------------------------------------------------------------
__device__ __align__(128) uint32_t g_pre[4][(size_t)MAX_BN * 64]; // fp16x2 pairs
__device__ __align__(128) float g_hacc[2][(size_t)MAX_BN * H_DIM];
__device__ __align__(128) float g_einv[2][MAX_N];
__device__ __align__(128) float g_pos_upd[(size_t)MAX_BN * 3];
__device__ __align__(128) uint32_t g_CpFrag[2][8192];     // fp16 hi, paired-ntile uint4 layout
__device__ __align__(128) float g_bpc[2][H_DIM];
__device__ __align__(128) float g_bcu[2][H_DIM];
__device__ __align__(128) uint32_t g_preFrag[4][16384];   // fp16 hi/lo uint4 layout
__device__ __align__(128) uint32_t g_nodeFrag[4][16384];  // wu1top,Cu0,Cu1,wu2

// silu via single-MUFU tanh.approx: silu(x) = 0.5x + 0.5x*tanh(x/2)
__device__ __forceinline__ float silu_f(float v) {
    float t;
    asm("tanh.approx.f32 %0, %1;" : "=f"(t) : "f"(0.5f * v));
    float hv = 0.5f * v;
    return fmaf(hv, t, hv);
}
__device__ __forceinline__ float tanh_f(float v) {
    float t;
    asm("tanh.approx.f32 %0, %1;" : "=f"(t) : "f"(v));
    return t;
}

// ---- fp16 mma.sync helpers --------------------------------------------------
__device__ __forceinline__ void mma_f16(float c[4], const uint32_t a[4],
                                        uint32_t b0, uint32_t b1) {
    asm volatile(
        "mma.sync.aligned.m16n8k16.row.col.f32.f16.f16.f32 "
        "{%0,%1,%2,%3}, {%4,%5,%6,%7}, {%8,%9}, {%0,%1,%2,%3};"
        : "+f"(c[0]), "+f"(c[1]), "+f"(c[2]), "+f"(c[3])
        : "r"(a[0]), "r"(a[1]), "r"(a[2]), "r"(a[3]), "r"(b0), "r"(b1));
}
__device__ __forceinline__ uint32_t pack_hh(__half lo, __half hi) {
    __half2 h = __halves2half2(lo, hi);
    return *reinterpret_cast<uint32_t*>(&h);
}
__device__ __forceinline__ uint32_t pack_ff(float e, float o) {
    __half2 h = __floats2half2_rn(e, o);
    return *reinterpret_cast<uint32_t*>(&h);
}
__device__ __forceinline__ float2 up2(uint32_t v) {
    return __half22float2(*reinterpret_cast<__half2*>(&v));
}

// ---------------------------------------------------------------------------
// combine_kernel: grid (65, 4), 128 thr.
// ---------------------------------------------------------------------------
__global__ void combine_kernel(
    const float* __restrict__ w2u, const float* __restrict__ wp1u,
    const float* __restrict__ b2u, const float* __restrict__ bp1u,
    const float* __restrict__ w2d, const float* __restrict__ wp1d,
    const float* __restrict__ b2d, const float* __restrict__ bp1d,
    const float* __restrict__ wu1,
    uint32_t* __restrict__ CpFrag, uint32_t* __restrict__ nodeFrag,
    float* __restrict__ bpc, float* __restrict__ bcu)
{
    const float* wu1b = wu1 + 128 * H_DIM;
    const float* A; const float* Bm; const float* bvec; const float* badd;
    uint32_t* C; float* bout; bool split;
    switch (blockIdx.y) {
        case 0:  A = w2u; Bm = wp1u; bvec = b2u; badd = bp1u;
                 C = CpFrag;               bout = bpc;         split = false; break;
        case 1:  A = w2d; Bm = wp1d; bvec = b2d; badd = bp1d;
                 C = CpFrag + 8192;        bout = bpc + H_DIM; split = false; break;
        case 2:  A = w2u; Bm = wu1b; bvec = b2u; badd = 0;
                 C = nodeFrag + 1 * 16384; bout = bcu;         split = true;  break;
        default: A = w2d; Bm = wu1b; bvec = b2d; badd = 0;
                 C = nodeFrag + 2 * 16384; bout = bcu + H_DIM; split = true;  break;
    }
    int i2 = blockIdx.x;
    int j  = threadIdx.x;
    if (i2 == 64) {
        float s = 0.f;
        #pragma unroll 8
        for (int k = 0; k < H_DIM; ++k) s += bvec[k] * Bm[k * H_DIM + j];
        bout[j] = s + (badd ? badd[j] : 0.f);
        return;
    }
    float s0 = 0.f, s1 = 0.f;
    const float* a0r = A + (size_t)(2 * i2) * H_DIM;
    const float* a1r = a0r + H_DIM;
    #pragma unroll 8
    for (int k = 0; k < H_DIM; ++k) {
        float b = Bm[k * H_DIM + j];
        s0 += a0r[k] * b;
        s1 += a1r[k] * b;
    }
    int ks = i2 >> 3, m = i2 & 7;
    int lanep = m & 3, reg = m >> 2;
    int nn = j & 7;
    if (split) {
        __half h0 = __float2half_rn(s0), h1 = __float2half_rn(s1);
        __half l0 = __float2half_rn(s0 - __half2float(h0));
        __half l1 = __float2half_rn(s1 - __half2float(h1));
        int ntile = j >> 3;
        size_t base = ((size_t)(ntile * 8 + ks) * 32 + nn * 4 + lanep) * 4;
        C[base + reg]     = pack_hh(h0, h1);
        C[base + 2 + reg] = pack_hh(l0, l1);
    } else {
        int ntile = j >> 3, pass = ntile >> 3, ntl = ntile & 7;
        size_t idx = (size_t)pass * 4096
                   + ((size_t)(ks * 4 + (ntl >> 1)) * 32 + nn * 4 + lanep) * 4
                   + (ntl & 1) * 2 + reg;
        C[idx] = pack_ff(s0, s1);
    }
}

// ---------------------------------------------------------------------------
// fragw_kernel: grid (64, 6), 128 thr.
// ---------------------------------------------------------------------------
__global__ void fragw_kernel(const float* __restrict__ w1u,
                             const float* __restrict__ w1d,
                             const float* __restrict__ wu1,
                             const float* __restrict__ wu2,
                             uint32_t* __restrict__ preFrag,
                             uint32_t* __restrict__ nodeFrag)
{
    int y = blockIdx.y;
    const float* W; uint32_t* out;
    switch (y) {
        case 0: W = w1u;                out = preFrag;              break;
        case 1: W = w1u + 128 * H_DIM;  out = preFrag + 16384;      break;
        case 2: W = w1d;                out = preFrag + 2 * 16384;  break;
        case 3: W = w1d + 128 * H_DIM;  out = preFrag + 3 * 16384;  break;
        case 4: W = wu1;                out = nodeFrag;             break;
        default: W = wu2;               out = nodeFrag + 3 * 16384; break;
    }
    int i2 = blockIdx.x;
    int j  = threadIdx.x;
    float x0 = W[(size_t)(2 * i2) * H_DIM + j];
    float x1 = W[(size_t)(2 * i2 + 1) * H_DIM + j];
    __half h0 = __float2half_rn(x0), h1 = __float2half_rn(x1);
    __half l0 = __float2half_rn(x0 - __half2float(h0));
    __half l1 = __float2half_rn(x1 - __half2float(h1));
    int ks = i2 >> 3, m = i2 & 7;
    int lanep = m & 3, reg = m >> 2;
    int ntile = j >> 3, nn = j & 7;
    size_t base = ((size_t)(ntile * 8 + ks) * 32 + nn * 4 + lanep) * 4;
    out[base + reg]     = pack_hh(h0, h1);
    out[base + 2 + reg] = pack_hh(l0, l1);
}

// ---------------------------------------------------------------------------
// pre_mma_kernel: 128-row blocks; outputs fp16x2 (unchanged from R14)
// ---------------------------------------------------------------------------
__global__ void __launch_bounds__(256)
pre_mma_kernel(const float* __restrict__ feat, const uint32_t* __restrict__ frag,
               uint32_t* __restrict__ p0, uint32_t* __restrict__ p1,
               uint32_t* __restrict__ p2, uint32_t* __restrict__ p3, int nRows)
{
    extern __shared__ uint32_t smu[];
    uint32_t* sAhi = smu;                  // [128][68] pairs
    uint32_t* sAlo = sAhi + 128 * PS1;

    const int tid = threadIdx.x;
    const int wid = tid >> 5, lane = tid & 31;
    const int wg = wid >> 2;               // matrix half
    const int rw = wid & 3;                // 32-row group
    const int ar = rw * 32 + (lane >> 2);
    const int ak = lane & 3;
    const int g0 = blockIdx.x * 128;

    #pragma unroll
    for (int p = 0; p < 16; ++p) {
        int idx = p * 256 + tid;
        int r = idx >> 5, c4 = idx & 31;
        float4 v = make_float4(0.f, 0.f, 0.f, 0.f);
        if (g0 + r < nRows)
            v = __ldg((const float4*)feat + (size_t)(g0 + r) * 32 + c4);
        __half hx = __float2half_rn(v.x), hy = __float2half_rn(v.y);
        __half hz = __float2half_rn(v.z), hw = __float2half_rn(v.w);
        *(uint2*)(sAhi + r * PS1 + 2 * c4) =
            make_uint2(pack_hh(hx, hy), pack_hh(hz, hw));
        *(uint2*)(sAlo + r * PS1 + 2 * c4) = make_uint2(
            pack_ff(v.x - __half2float(hx), v.y - __half2float(hy)),
            pack_ff(v.z - __half2float(hz), v.w - __half2float(hw)));
    }
    __syncthreads();

    uint32_t* outs[4] = {p0, p1, p2, p3};

    #pragma unroll
    for (int m2 = 0; m2 < 2; ++m2) {
        int m = wg * 2 + m2;
        const uint4* Bm = (const uint4*)frag + (size_t)m * 4096;
        uint32_t* out = outs[m];
        #pragma unroll
        for (int pass = 0; pass < 2; ++pass) {
            float c[2][8][4];
            #pragma unroll
            for (int t = 0; t < 2; ++t)
                #pragma unroll
                for (int nt = 0; nt < 8; ++nt)
                    #pragma unroll
                    for (int q = 0; q < 4; ++q) c[t][nt][q] = 0.f;

            #pragma unroll 2
            for (int ks = 0; ks < 8; ++ks) {
                int kp = ks * 8 + ak;
                uint32_t ah0[4], al0[4], ah1[4], al1[4];
                ah0[0] = sAhi[ar * PS1 + kp];
                ah0[1] = sAhi[(ar + 8) * PS1 + kp];
                ah0[2] = sAhi[ar * PS1 + kp + 4];
                ah0[3] = sAhi[(ar + 8) * PS1 + kp + 4];
                al0[0] = sAlo[ar * PS1 + kp];
                al0[1] = sAlo[(ar + 8) * PS1 + kp];
                al0[2] = sAlo[ar * PS1 + kp + 4];
                al0[3] = sAlo[(ar + 8) * PS1 + kp + 4];
                ah1[0] = sAhi[(ar + 16) * PS1 + kp];
                ah1[1] = sAhi[(ar + 24) * PS1 + kp];
                ah1[2] = sAhi[(ar + 16) * PS1 + kp + 4];
                ah1[3] = sAhi[(ar + 24) * PS1 + kp + 4];
                al1[0] = sAlo[(ar + 16) * PS1 + kp];
                al1[1] = sAlo[(ar + 24) * PS1 + kp];
                al1[2] = sAlo[(ar + 16) * PS1 + kp + 4];
                al1[3] = sAlo[(ar + 24) * PS1 + kp + 4];
                #pragma unroll
                for (int nt = 0; nt < 8; ++nt) {
                    int ntile = pass * 8 + nt;
                    uint4 v = __ldg(Bm + (size_t)(ntile * 8 + ks) * 32 + lane);
                    mma_f16(c[0][nt], ah0, v.x, v.y);
                    mma_f16(c[0][nt], al0, v.x, v.y);
                    mma_f16(c[0][nt], ah0, v.z, v.w);
                    mma_f16(c[1][nt], ah1, v.x, v.y);
                    mma_f16(c[1][nt], al1, v.x, v.y);
                    mma_f16(c[1][nt], ah1, v.z, v.w);
                }
            }
            #pragma unroll
            for (int t = 0; t < 2; ++t) {
                int rowA = g0 + ar + t * 16, rowB = rowA + 8;
                #pragma unroll
                for (int nt = 0; nt < 8; ++nt) {
                    int cp = ((pass * 8 + nt) * 8 + 2 * ak) >> 1;  // uint32 index
                    if (rowA < nRows)
                        out[(size_t)rowA * 64 + cp] = pack_ff(c[t][nt][0], c[t][nt][1]);
                    if (rowB < nRows)
                        out[(size_t)rowB * 64 + cp] = pack_ff(c[t][nt][2], c[t][nt][3]);
                }
            }
        }
    }
}

// ---------------------------------------------------------------------------
// edge_mma_kernel: unchanged from R14 (256 edges/block, 2 CTAs/SM)
// ---------------------------------------------------------------------------
struct EdgeDir {
    const uint32_t* pre_a; const uint32_t* pre_b;   // fp16x2 rows (64 u32/row)
    const int* ei; const float* deg;
    const float* w1; const float* b1;
    const uint32_t* CpFrag; const float* bpc;
    const float* wp2; const float* bp2;
    float* hacc; float* einv;
};
struct EdgeParams { EdgeDir d[2]; };

__global__ void __launch_bounds__(256, 2)
edge_mma_kernel(EdgeParams P, const float* __restrict__ pos,
                float* __restrict__ pos_upd, int nE, int N)
{
    extern __shared__ uint32_t smu[];
    uint32_t* sHid = smu;                       // [256][68] fp16x2 pairs
    float* s_w1c = (float*)(smu + 256 * PS1);
    float* s_b1  = s_w1c + 128;
    float* s_bpc = s_b1 + 128;
    float* s_wp2 = s_bpc + 128;
    float* s_rel = s_wp2 + 128;                 // [256*3]
    float* s_dist= s_rel + 768;
    float* s_inv = s_dist + 256;
    float* s_p   = s_inv + 256;                 // [256]
    int*   s_src = (int*)(s_p + 256);
    int*   s_dst = s_src + 256;

    const EdgeDir& D = P.d[blockIdx.z];
    const int tid  = threadIdx.x;
    const int wid  = tid >> 5;
    const int lane = tid & 31;
    const int b    = blockIdx.y;
    const int e0   = blockIdx.x * TEC;
    const size_t bN = (size_t)b * N;

    {
        int e = e0 + tid;
        int s = 0, d = 0;
        float x0 = 0.f, x1 = 0.f, x2 = 0.f, dist = 0.f, inv = 0.f;
        if (e < nE) {
            s = D.ei[e];
            d = D.ei[nE + e];
            const float* ps = pos + (bN + s) * 3;
            const float* pd = pos + (bN + d) * 3;
            x0 = ps[0] - pd[0];
            x1 = ps[1] - pd[1];
            x2 = ps[2] - pd[2];
            dist = sqrtf(x0 * x0 + x1 * x1 + x2 * x2);
            inv  = 1.0f / fmaxf(D.deg[d], 1.0f);
        }
        s_src[tid] = s; s_dst[tid] = d;
        s_rel[tid * 3 + 0] = x0; s_rel[tid * 3 + 1] = x1; s_rel[tid * 3 + 2] = x2;
        s_dist[tid] = dist; s_inv[tid] = inv;
        if (tid < 128) {
            s_w1c[tid] = D.w1[256 * H_DIM + tid];
            s_b1[tid]  = D.b1[tid];
            s_bpc[tid] = D.bpc[tid];
            s_wp2[tid] = D.wp2[tid];
        }
    }
    __syncthreads();

    #pragma unroll
    for (int p = 0; p < 32; p += 4) {
        uint2 va[4], vb[4];
        #pragma unroll
        for (int q = 0; q < 4; ++q) {
            int r = (p + q) * 8 + wid;
            va[q] = __ldg((const uint2*)D.pre_a + (size_t)(bN + s_src[r]) * 32 + lane);
            vb[q] = __ldg((const uint2*)D.pre_b + (size_t)(bN + s_dst[r]) * 32 + lane);
        }
        #pragma unroll
        for (int q = 0; q < 4; ++q) {
            int r = (p + q) * 8 + wid;
            float dd = s_dist[r], inv = s_inv[r];
            float4 wc = *(const float4*)(s_w1c + lane * 4);
            float4 bb = *(const float4*)(s_b1 + lane * 4);
            float2 a01 = up2(va[q].x), a23 = up2(va[q].y);
            float2 b01 = up2(vb[q].x), b23 = up2(vb[q].y);
            float h0 = silu_f(a01.x + b01.x + dd * wc.x + bb.x);
            float h1 = silu_f(a01.y + b01.y + dd * wc.y + bb.y);
            float h2 = silu_f(a23.x + b23.x + dd * wc.z + bb.z);
            float h3 = silu_f(a23.y + b23.y + dd * wc.w + bb.w);
            *(uint2*)(sHid + r * PS1 + 2 * lane) =
                make_uint2(pack_ff(h0, h1), pack_ff(h2, h3));
            float* gp = D.hacc + (bN + s_dst[r]) * H_DIM + lane * 4;
            asm volatile("red.global.add.v4.f32 [%0], {%1, %2, %3, %4};"
                         :: "l"(gp), "f"(h0 * inv), "f"(h1 * inv),
                            "f"(h2 * inv), "f"(h3 * inv) : "memory");
        }
    }
    if (b == 0 && (e0 + tid) < nE)
        atomicAdd(&D.einv[s_dst[tid]], s_inv[tid]);
    __syncthreads();

    const int arb = wid * 32 + (lane >> 2);
    const int ak  = lane & 3;
    float sum[4] = {0.f, 0.f, 0.f, 0.f};
    const uint4* Cp4 = (const uint4*)D.CpFrag;

    #pragma unroll
    for (int pass = 0; pass < 2; ++pass) {
        float c[2][8][4];
        #pragma unroll
        for (int t = 0; t < 2; ++t)
            #pragma unroll
            for (int nt = 0; nt < 8; ++nt)
                #pragma unroll
                for (int q = 0; q < 4; ++q) c[t][nt][q] = 0.f;

        #pragma unroll 2
        for (int ks = 0; ks < 8; ++ks) {
            int kp = ks * 8 + ak;
            uint4 bv[4];
            #pragma unroll
            for (int ntp = 0; ntp < 4; ++ntp)
                bv[ntp] = __ldg(Cp4 + (size_t)pass * 1024
                                + (size_t)(ks * 4 + ntp) * 32 + lane);
            #pragma unroll
            for (int t = 0; t < 2; ++t) {
                int ar = arb + t * 16;
                uint32_t a[4];
                a[0] = sHid[ar * PS1 + kp];
                a[1] = sHid[(ar + 8) * PS1 + kp];
                a[2] = sHid[ar * PS1 + kp + 4];
                a[3] = sHid[(ar + 8) * PS1 + kp + 4];
                #pragma unroll
                for (int ntp = 0; ntp < 4; ++ntp) {
                    mma_f16(c[t][2 * ntp],     a, bv[ntp].x, bv[ntp].y);
                    mma_f16(c[t][2 * ntp + 1], a, bv[ntp].z, bv[ntp].w);
                }
            }
        }
        #pragma unroll
        for (int t = 0; t < 2; ++t) {
            #pragma unroll
            for (int nt = 0; nt < 8; ++nt) {
                int cb = pass * 64 + nt * 8 + 2 * ak;
                float w0 = s_wp2[cb], w1v = s_wp2[cb + 1];
                float q0 = s_bpc[cb], q1 = s_bpc[cb + 1];
                sum[2 * t]     += silu_f(c[t][nt][0] + q0) * w0
                                + silu_f(c[t][nt][1] + q1) * w1v;
                sum[2 * t + 1] += silu_f(c[t][nt][2] + q0) * w0
                                + silu_f(c[t][nt][3] + q1) * w1v;
            }
        }
    }

    #pragma unroll
    for (int i = 0; i < 4; ++i) {
        sum[i] += __shfl_xor_sync(0xFFFFFFFFu, sum[i], 1);
        sum[i] += __shfl_xor_sync(0xFFFFFFFFu, sum[i], 2);
    }
    if (ak == 0) {
        s_p[arb]      = sum[0];
        s_p[arb + 8]  = sum[1];
        s_p[arb + 16] = sum[2];
        s_p[arb + 24] = sum[3];
    }
    __syncthreads();

    if ((e0 + tid) < nE) {
        float w = tanh_f(s_p[tid] + D.bp2[0]);
        int d = s_dst[tid];
        float* pp = pos_upd + (bN + d) * 3;
        atomicAdd(&pp[0], w * s_rel[tid * 3 + 0]);
        atomicAdd(&pp[1], w * s_rel[tid * 3 + 1]);
        atomicAdd(&pp[2], w * s_rel[tid * 3 + 2]);
    }
}

// ---------------------------------------------------------------------------
// node2_mma_kernel: split-fp16 node update (R14 shape) + fused pos epilogue
// ---------------------------------------------------------------------------
__global__ void __launch_bounds__(256)
node2_mma_kernel(const float* __restrict__ feat,
                 const float* __restrict__ hacc0, const float* __restrict__ hacc1,
                 const uint32_t* __restrict__ nodeFrag,
                 const float* __restrict__ einv0, const float* __restrict__ einv1,
                 const float* __restrict__ bcu0, const float* __restrict__ bcu1,
                 const float* __restrict__ bu1,  const float* __restrict__ bu2,
                 float* __restrict__ outf,
                 const float* __restrict__ posIn, const float* __restrict__ pos_upd,
                 float* __restrict__ outp, int N, int nRows)
{
    extern __shared__ uint32_t smu[];
    uint32_t* sAhi = smu;                   // [64][68]
    uint32_t* sAlo = sAhi + 64 * PS1;
    float* s_eU   = (float*)(smu + 2 * 64 * PS1);   // [64]
    float* s_eD   = s_eU + 64;
    float* s_bias = s_eD + 64;              // 4*128

    const int tid = threadIdx.x;
    const int wid = tid >> 5, lane = tid & 31;
    const int rg = wid & 3, cg = wid >> 2;
    const int ar = rg * 16 + (lane >> 2);
    const int ak = lane & 3;
    const int g0 = blockIdx.x * 64;

    // fused pos epilogue (independent of the GEMM below; pos_upd final here)
    if (tid < 192) {
        int i = g0 * 3 + tid;
        if (i < nRows * 3) outp[i] = posIn[i] + 0.5f * pos_upd[i];
    }

    if (tid < 64) {
        int g = g0 + tid;
        float eu = 0.f, ed = 0.f;
        if (g < nRows) {
            int node = g % N;
            eu = einv0[node];
            ed = einv1[node];
        }
        s_eU[tid] = eu; s_eD[tid] = ed;
    }
    if (tid < 128) {
        s_bias[tid]       = bu1[tid];
        s_bias[128 + tid] = bcu0[tid];
        s_bias[256 + tid] = bcu1[tid];
        s_bias[384 + tid] = bu2[tid];
    }

    float c[2][4][4];
    #pragma unroll
    for (int p = 0; p < 2; ++p)
        #pragma unroll
        for (int nt = 0; nt < 4; ++nt)
            #pragma unroll
            for (int q = 0; q < 4; ++q) c[p][nt][q] = 0.f;

    for (int m = 0; m < 3; ++m) {
        const float* src = (m == 0) ? feat : (m == 1) ? hacc0 : hacc1;
        __syncthreads();
        #pragma unroll
        for (int p = 0; p < 8; ++p) {
            int idx = p * 256 + tid;
            int r = idx >> 5, c4 = idx & 31;
            float4 v = make_float4(0.f, 0.f, 0.f, 0.f);
            if (g0 + r < nRows)
                v = __ldg((const float4*)src + (size_t)(g0 + r) * 32 + c4);
            __half hx = __float2half_rn(v.x), hy = __float2half_rn(v.y);
            __half hz = __float2half_rn(v.z), hw = __float2half_rn(v.w);
            *(uint2*)(sAhi + r * PS1 + 2 * c4) =
                make_uint2(pack_hh(hx, hy), pack_hh(hz, hw));
            *(uint2*)(sAlo + r * PS1 + 2 * c4) = make_uint2(
                pack_ff(v.x - __half2float(hx), v.y - __half2float(hy)),
                pack_ff(v.z - __half2float(hz), v.w - __half2float(hw)));
        }
        __syncthreads();

        const uint4* Bm = (const uint4*)(nodeFrag + (size_t)m * 16384);
        #pragma unroll 2
        for (int ks = 0; ks < 8; ++ks) {
            int kp = ks * 8 + ak;
            uint32_t ah[4], al[4];
            ah[0] = sAhi[ar * PS1 + kp];
            ah[1] = sAhi[(ar + 8) * PS1 + kp];
            ah[2] = sAhi[ar * PS1 + kp + 4];
            ah[3] = sAhi[(ar + 8) * PS1 + kp + 4];
            al[0] = sAlo[ar * PS1 + kp];
            al[1] = sAlo[(ar + 8) * PS1 + kp];
            al[2] = sAlo[ar * PS1 + kp + 4];
            al[3] = sAlo[(ar + 8) * PS1 + kp + 4];
            #pragma unroll
            for (int pass = 0; pass < 2; ++pass) {
                #pragma unroll
                for (int nt = 0; nt < 4; ++nt) {
                    int ntile = pass * 8 + cg * 4 + nt;
                    uint4 v = __ldg(Bm + (size_t)(ntile * 8 + ks) * 32 + lane);
                    mma_f16(c[pass][nt], ah, v.x, v.y);
                    mma_f16(c[pass][nt], al, v.x, v.y);
                    mma_f16(c[pass][nt], ah, v.z, v.w);
                }
            }
        }
    }
    __syncthreads();
    {
        float eu0 = s_eU[ar],     ed0 = s_eD[ar];
        float eu1 = s_eU[ar + 8], ed1 = s_eD[ar + 8];
        #pragma unroll
        for (int pass = 0; pass < 2; ++pass) {
            #pragma unroll
            for (int nt = 0; nt < 4; ++nt) {
                int col = (pass * 8 + cg * 4 + nt) * 8 + 2 * ak;
                int kp  = col >> 1;
                float bA = s_bias[col],        bB = s_bias[col + 1];
                float cA0 = s_bias[128 + col], cA1 = s_bias[128 + col + 1];
                float cB0 = s_bias[256 + col], cB1 = s_bias[256 + col + 1];
                float v00 = silu_f(c[pass][nt][0] + bA + eu0 * cA0 + ed0 * cB0);
                float v01 = silu_f(c[pass][nt][1] + bB + eu0 * cA1 + ed0 * cB1);
                float v10 = silu_f(c[pass][nt][2] + bA + eu1 * cA0 + ed1 * cB0);
                float v11 = silu_f(c[pass][nt][3] + bB + eu1 * cA1 + ed1 * cB1);
                __half h00 = __float2half_rn(v00), h01 = __float2half_rn(v01);
                __half h10 = __float2half_rn(v10), h11 = __float2half_rn(v11);
                sAhi[ar * PS1 + kp]       = pack_hh(h00, h01);
                sAhi[(ar + 8) * PS1 + kp] = pack_hh(h10, h11);
                sAlo[ar * PS1 + kp] = pack_ff(
                    v00 - __half2float(h00), v01 - __half2float(h01));
                sAlo[(ar + 8) * PS1 + kp] = pack_ff(
                    v10 - __half2float(h10), v11 - __half2float(h11));
            }
        }
    }
    __syncthreads();

    #pragma unroll
    for (int p = 0; p < 2; ++p)
        #pragma unroll
        for (int nt = 0; nt < 4; ++nt)
            #pragma unroll
            for (int q = 0; q < 4; ++q) c[p][nt][q] = 0.f;

    {
        const uint4* Bm = (const uint4*)(nodeFrag + (size_t)3 * 16384);
        #pragma unroll 2
        for (int ks = 0; ks < 8; ++ks) {
            int kp = ks * 8 + ak;
            uint32_t ah[4], al[4];
            ah[0] = sAhi[ar * PS1 + kp];
            ah[1] = sAhi[(ar + 8) * PS1 + kp];
            ah[2] = sAhi[ar * PS1 + kp + 4];
            ah[3] = sAhi[(ar + 8) * PS1 + kp + 4];
            al[0] = sAlo[ar * PS1 + kp];
            al[1] = sAlo[(ar + 8) * PS1 + kp];
            al[2] = sAlo[ar * PS1 + kp + 4];
            al[3] = sAlo[(ar + 8) * PS1 + kp + 4];
            #pragma unroll
            for (int pass = 0; pass < 2; ++pass) {
                #pragma unroll
                for (int nt = 0; nt < 4; ++nt) {
                    int ntile = pass * 8 + cg * 4 + nt;
                    uint4 v = __ldg(Bm + (size_t)(ntile * 8 + ks) * 32 + lane);
                    mma_f16(c[pass][nt], ah, v.x, v.y);
                    mma_f16(c[pass][nt], al, v.x, v.y);
                    mma_f16(c[pass][nt], ah, v.z, v.w);
                }
            }
        }
    }
    {
        int gA = g0 + ar, gB = g0 + ar + 8;
        #pragma unroll
        for (int pass = 0; pass < 2; ++pass) {
            #pragma unroll
            for (int nt = 0; nt < 4; ++nt) {
                int col = (pass * 8 + cg * 4 + nt) * 8 + 2 * ak;
                float bA = s_bias[384 + col], bB = s_bias[384 + col + 1];
                if (gA < nRows) {
                    size_t o = (size_t)gA * H_DIM + col;
                    float2 f = *(const float2*)&feat[o];
                    *(float2*)&outf[o] = make_float2(
                        f.x + c[pass][nt][0] + bA, f.y + c[pass][nt][1] + bB);
                }
                if (gB < nRows) {
                    size_t o = (size_t)gB * H_DIM + col;
                    float2 f = *(const float2*)&feat[o];
                    *(float2*)&outf[o] = make_float2(
                        f.x + c[pass][nt][2] + bA, f.y + c[pass][nt][3] + bB);
                }
            }
        }
    }
}

extern "C" void kernel_launch(void* const* d_in, const int* in_sizes, int n_in,
                              void* d_out, int out_size)
{
    const float* feat   = (const float*)d_in[0];
    const float* pos    = (const float*)d_in[1];
    const int*   ei_up  = (const int*)d_in[2];
    const int*   ei_dn  = (const int*)d_in[3];
    const float* deg_up = (const float*)d_in[4];
    const float* deg_dn = (const float*)d_in[5];

    const float* w1u  = (const float*)d_in[6];
    const float* b1u  = (const float*)d_in[7];
    const float* w2u  = (const float*)d_in[8];
    const float* b2u  = (const float*)d_in[9];
    const float* wp1u = (const float*)d_in[10];
    const float* bp1u = (const float*)d_in[11];
    const float* wp2u = (const float*)d_in[12];
    const float* bp2u = (const float*)d_in[13];

    const float* w1d  = (const float*)d_in[14];
    const float* b1d  = (const float*)d_in[15];
    const float* w2d  = (const float*)d_in[16];
    const float* b2d  = (const float*)d_in[17];
    const float* wp1d = (const float*)d_in[18];
    const float* bp1d = (const float*)d_in[19];
    const float* wp2d = (const float*)d_in[20];
    const float* bp2d = (const float*)d_in[21];

    const float* wu1 = (const float*)d_in[22];
    const float* bu1 = (const float*)d_in[23];
    const float* wu2 = (const float*)d_in[24];
    const float* bu2 = (const float*)d_in[25];

    int E = in_sizes[2] / 2;
    int N = in_sizes[4];
    int B = in_sizes[0] / (N * H_DIM);
    int nRows = B * N;

    float *hacc, *einv, *pos_upd, *bpc, *bcu;
    uint32_t *pre, *CpFrag, *preFrag, *nodeFrag;
    cudaGetSymbolAddress((void**)&pre,      g_pre);
    cudaGetSymbolAddress((void**)&hacc,     g_hacc);
    cudaGetSymbolAddress((void**)&einv,     g_einv);
    cudaGetSymbolAddress((void**)&pos_upd,  g_pos_upd);
    cudaGetSymbolAddress((void**)&CpFrag,   g_CpFrag);
    cudaGetSymbolAddress((void**)&bpc,      g_bpc);
    cudaGetSymbolAddress((void**)&bcu,      g_bcu);
    cudaGetSymbolAddress((void**)&preFrag,  g_preFrag);
    cudaGetSymbolAddress((void**)&nodeFrag, g_nodeFrag);

    const size_t PS = (size_t)MAX_BN * 64;
    uint32_t* pre_au = pre;
    uint32_t* pre_bu = pre + PS;
    uint32_t* pre_ad = pre + 2 * PS;
    uint32_t* pre_bd = pre + 3 * PS;
    const size_t HPS = (size_t)MAX_BN * H_DIM;
    float* hacc_u = hacc;
    float* hacc_d = hacc + HPS;
    float* einv_u = einv;
    float* einv_d = einv + MAX_N;

    cudaMemsetAsync(hacc, 0, 2 * HPS * sizeof(float));
    cudaMemsetAsync(einv, 0, 2 * MAX_N * sizeof(float));
    cudaMemsetAsync(pos_upd, 0, (size_t)nRows * 3 * sizeof(float));

    int smemPre  = 2 * 128 * PS1 * 4;                           // 69632 B
    int smemEdge = 256 * PS1 * 4
                 + (512 + 768 + 256 + 256 + 256) * 4 + 512 * 4; // 79872 B
    int smemNode = (2 * 64 * PS1 + 128 + 512) * 4;              // 37376 B
    cudaFuncSetAttribute(pre_mma_kernel,
                         cudaFuncAttributeMaxDynamicSharedMemorySize, smemPre);
    cudaFuncSetAttribute(edge_mma_kernel,
                         cudaFuncAttributeMaxDynamicSharedMemorySize, smemEdge);
    cudaFuncSetAttribute(node2_mma_kernel,
                         cudaFuncAttributeMaxDynamicSharedMemorySize, smemNode);

    combine_kernel<<<dim3(65, 4), H_DIM>>>(
        w2u, wp1u, b2u, bp1u, w2d, wp1d, b2d, bp1d, wu1,
        CpFrag, nodeFrag, bpc, bcu);

    fragw_kernel<<<dim3(64, 6), H_DIM>>>(w1u, w1d, wu1, wu2,
                                         preFrag, nodeFrag);

    pre_mma_kernel<<<(nRows + 127) / 128, 256, smemPre>>>(
        feat, preFrag, pre_au, pre_bu, pre_ad, pre_bd, nRows);

    EdgeParams EP;
    EP.d[0] = { pre_au, pre_bu, ei_up, deg_up, w1u, b1u,
                CpFrag,        bpc,         wp2u, bp2u, hacc_u, einv_u };
    EP.d[1] = { pre_ad, pre_bd, ei_dn, deg_dn, w1d, b1d,
                CpFrag + 8192, bpc + H_DIM, wp2d, bp2d, hacc_d, einv_d };

    dim3 egrid((E + TEC - 1) / TEC, B, 2);
    edge_mma_kernel<<<egrid, 256, smemEdge>>>(EP, pos, pos_upd, E, N);

    size_t featN = (size_t)nRows * H_DIM;
    node2_mma_kernel<<<(nRows + 63) / 64, 256, smemNode>>>(
        feat, hacc_u, hacc_d, nodeFrag, einv_u, einv_d,
        bcu, bcu + H_DIM, bu1, bu2, (float*)d_out,
        pos, pos_upd, (float*)d_out + featN, N, nRows);
}